// round 1
// baseline (speedup 1.0000x reference)
#include <cuda_runtime.h>
#include <cstdint>
#include <cstddef>

#define NT        32768          // tokens = B*T
#define DM        1024           // d_model = expert_dim
#define NE        8
#define ROWS_MAX  (2*NT + NE*128)
#define MAX_TILES (ROWS_MAX/128)
#define BM 128
#define BN 128
#define BK 32
#define SROW 136                 // smem row stride (words) for conflict-free swizzle

// -------------------- device scratch (static, no allocs) --------------------
__device__ int   g_count[NE];
__device__ int   g_cursor[NE];
__device__ int   g_base[NE+1];
__device__ int   g_tileExpert[MAX_TILES];
__device__ int   g_rowToken[ROWS_MAX];
__device__ float g_rowWeight[ROWS_MAX];
__device__ int   g_tokE[NT*2];
__device__ float g_tokS[NT*2];
__device__ float g_h[(size_t)ROWS_MAX * DM];   // ~272 MB fp32 scratch

// -------------------- init: zero counters + output, poison row lists -------
__global__ void k_init(float* __restrict__ out) {
    int i = blockIdx.x * blockDim.x + threadIdx.x;
    int nth = gridDim.x * blockDim.x;
    if (i < NE) g_count[i] = 0;
    for (int j = i; j < ROWS_MAX; j += nth) { g_rowToken[j] = -1; g_rowWeight[j] = 0.f; }
    float4 z = make_float4(0.f, 0.f, 0.f, 0.f);
    float4* o4 = (float4*)out;
    int n4 = NT * DM / 4;
    for (int j = i; j < n4; j += nth) o4[j] = z;
}

// -------------------- gating: one warp per token, fp32 exact ---------------
__global__ void k_gate(const float* __restrict__ x,
                       const float* __restrict__ gw,
                       const float* __restrict__ gb) {
    int warp = (blockIdx.x * blockDim.x + threadIdx.x) >> 5;
    int lane = threadIdx.x & 31;
    if (warp >= NT) return;
    const float* xr = x + (size_t)warp * DM;
    float acc[NE];
#pragma unroll
    for (int e = 0; e < NE; e++) acc[e] = 0.f;
    for (int k = lane; k < DM; k += 32) {
        float xv = xr[k];
#pragma unroll
        for (int e = 0; e < NE; e++) acc[e] += xv * gw[k * NE + e];
    }
#pragma unroll
    for (int e = 0; e < NE; e++)
#pragma unroll
        for (int off = 16; off; off >>= 1)
            acc[e] += __shfl_xor_sync(0xffffffffu, acc[e], off);
    if (lane == 0) {
#pragma unroll
        for (int e = 0; e < NE; e++) acc[e] += gb[e];
        int e0 = 0; float s0 = acc[0];
#pragma unroll
        for (int e = 1; e < NE; e++) if (acc[e] > s0) { s0 = acc[e]; e0 = e; }
        int e1 = -1; float s1 = -3.4e38f;
#pragma unroll
        for (int e = 0; e < NE; e++) if (e != e0 && acc[e] > s1) { s1 = acc[e]; e1 = e; }
        g_tokE[2*warp]   = e0;  g_tokS[2*warp]   = s0;
        g_tokE[2*warp+1] = e1;  g_tokS[2*warp+1] = s1;
        atomicAdd(&g_count[e0], 1);
        atomicAdd(&g_count[e1], 1);
    }
}

// -------------------- prefix sum (128-aligned) + tile->expert map ----------
__global__ void k_prefix() {
    if (threadIdx.x == 0) {
        int b = 0; g_base[0] = 0;
        for (int e = 0; e < NE; e++) {
            g_cursor[e] = b;
            b += ((g_count[e] + 127) >> 7) << 7;
            g_base[e+1] = b;
        }
    }
    __syncthreads();
    for (int t = threadIdx.x; t < MAX_TILES; t += blockDim.x) {
        int r = t << 7;
        int e = -1;
        for (int q = 0; q < NE; q++)
            if (r >= g_base[q] && r < g_base[q+1]) e = q;
        g_tileExpert[t] = e;
    }
}

// -------------------- scatter assignments into expert segments -------------
__global__ void k_scatter() {
    int i = blockIdx.x * blockDim.x + threadIdx.x;
    if (i >= NT * 2) return;
    int e = g_tokE[i];
    int p = atomicAdd(&g_cursor[e], 1);
    g_rowToken[p]  = i >> 1;
    g_rowWeight[p] = g_tokS[i];
}

// -------------------- tf32 MMA helpers -------------------------------------
__device__ __forceinline__ uint32_t f2tf(float f) {
    uint32_t r; asm("cvt.rna.tf32.f32 %0, %1;" : "=r"(r) : "f"(f)); return r;
}
__device__ __forceinline__ int swz(int k, int r) {
    // word offset with XOR swizzle: conflict-free for both the k-vectorized
    // stores (k = 4q+j per lane) and the fragment loads (k const per instr)
    return k * SROW + (r ^ ((k >> 2) << 2));
}
__device__ __forceinline__ void mma8(float (&c)[4], const uint32_t (&a)[4], const uint32_t (&b)[2]) {
    asm volatile("mma.sync.aligned.m16n8k8.row.col.f32.tf32.tf32.f32 "
                 "{%0,%1,%2,%3}, {%4,%5,%6,%7}, {%8,%9}, {%0,%1,%2,%3};"
                 : "+f"(c[0]), "+f"(c[1]), "+f"(c[2]), "+f"(c[3])
                 : "r"(a[0]), "r"(a[1]), "r"(a[2]), "r"(a[3]),
                   "r"(b[0]), "r"(b[1]));
}

// -------------------- grouped GEMM: PHASE 1 = x@w1+relu, PHASE 2 = h@w2 ----
template<int PHASE>
__global__ void __launch_bounds__(256)
k_gemm(const float* __restrict__ X,      // phase1: x [NT, DM]
       const float* __restrict__ W,      // [NE, 1024, 1024] (K-major rows)
       const float* __restrict__ Bias,   // [NE, 1024]
       float* __restrict__ Out) {        // phase2: out [NT, DM]
    int tile = blockIdx.x;
    int e = g_tileExpert[tile];
    if (e < 0) return;
    int rowBase = tile * BM;
    int colBase = blockIdx.y * BN;

    __shared__ uint32_t As[BK * SROW];
    __shared__ uint32_t Bs[BK * SROW];

    int tid  = threadIdx.x;
    int lane = tid & 31, warp = tid >> 5;
    int warpM = warp >> 2, warpN = warp & 3;     // 2 x 4 warp grid
    int g = lane >> 2, tig = lane & 3;

    // A gmem: thread loads float4 at (row = tid/8 + 32*it, k = (tid%8)*4)
    int aRow0 = tid >> 3;
    int aK    = (tid & 7) * 4;
    const float* aPtr[4];
#pragma unroll
    for (int it = 0; it < 4; it++) {
        int r = aRow0 + 32 * it;
        if (PHASE == 1) {
            int tok = g_rowToken[rowBase + r];
            aPtr[it] = (tok >= 0) ? (X + (size_t)tok * DM + aK) : nullptr;
        } else {
            aPtr[it] = g_h + (size_t)(rowBase + r) * DM + aK;
        }
    }
    const float* wBase = W + ((size_t)e << 20);
    int bR0 = tid >> 5;            // k row (const per warp)
    int bC  = (lane) * 4;          // 4 consecutive cols

    float c[4][4][4];
#pragma unroll
    for (int i = 0; i < 4; i++)
#pragma unroll
        for (int j = 0; j < 4; j++)
#pragma unroll
            for (int q = 0; q < 4; q++) c[i][j][q] = 0.f;

    for (int kk = 0; kk < 1024; kk += BK) {
        // ---- load A tile (gathered rows), cvt to tf32, swizzled stores ----
#pragma unroll
        for (int it = 0; it < 4; it++) {
            float4 v;
            if (aPtr[it]) v = *(const float4*)(aPtr[it] + kk);
            else          v = make_float4(0.f, 0.f, 0.f, 0.f);
            int r = aRow0 + 32 * it;
            As[swz(aK + 0, r)] = f2tf(v.x);
            As[swz(aK + 1, r)] = f2tf(v.y);
            As[swz(aK + 2, r)] = f2tf(v.z);
            As[swz(aK + 3, r)] = f2tf(v.w);
        }
        // ---- load B tile (w rows are K-major), vector swizzled stores -----
#pragma unroll
        for (int it = 0; it < 4; it++) {
            int r = bR0 + 8 * it;
            float4 v = *(const float4*)(wBase + (size_t)(kk + r) * 1024 + colBase + bC);
            uint4 t;
            t.x = f2tf(v.x); t.y = f2tf(v.y); t.z = f2tf(v.z); t.w = f2tf(v.w);
            *(uint4*)&Bs[swz(r, bC)] = t;
        }
        __syncthreads();
        // ---- mainloop: 4 k8-steps, 4x4 mma atoms per warp -----------------
#pragma unroll
        for (int k8 = 0; k8 < BK; k8 += 8) {
            int kA = k8 + tig;
            uint32_t a[4][4], b[4][2];
#pragma unroll
            for (int ma = 0; ma < 4; ma++) {
                int r0 = warpM * 64 + ma * 16 + g;
                a[ma][0] = As[swz(kA,     r0)];
                a[ma][1] = As[swz(kA,     r0 + 8)];
                a[ma][2] = As[swz(kA + 4, r0)];
                a[ma][3] = As[swz(kA + 4, r0 + 8)];
            }
#pragma unroll
            for (int nb = 0; nb < 4; nb++) {
                int cn = warpN * 32 + nb * 8 + g;
                b[nb][0] = Bs[swz(kA,     cn)];
                b[nb][1] = Bs[swz(kA + 4, cn)];
            }
#pragma unroll
            for (int ma = 0; ma < 4; ma++)
#pragma unroll
                for (int nb = 0; nb < 4; nb++)
                    mma8(c[ma][nb], a[ma], b[nb]);
        }
        __syncthreads();
    }

    // ---------------- epilogue ----------------
#pragma unroll
    for (int ma = 0; ma < 4; ma++) {
#pragma unroll
        for (int half = 0; half < 2; half++) {
            int r = warpM * 64 + ma * 16 + g + half * 8;
            int grow = rowBase + r;
            if (PHASE == 1) {
#pragma unroll
                for (int nb = 0; nb < 4; nb++) {
                    int cn = colBase + warpN * 32 + nb * 8 + tig * 2;
                    float v0 = c[ma][nb][half * 2 + 0] + Bias[e * 1024 + cn];
                    float v1 = c[ma][nb][half * 2 + 1] + Bias[e * 1024 + cn + 1];
                    v0 = v0 > 0.f ? v0 : 0.f;
                    v1 = v1 > 0.f ? v1 : 0.f;
                    *(float2*)&g_h[(size_t)grow * DM + cn] = make_float2(v0, v1);
                }
            } else {
                int tok = g_rowToken[grow];
                if (tok >= 0) {
                    float w = g_rowWeight[grow];
#pragma unroll
                    for (int nb = 0; nb < 4; nb++) {
                        int cn = colBase + warpN * 32 + nb * 8 + tig * 2;
                        float v0 = (c[ma][nb][half * 2 + 0] + Bias[e * 1024 + cn]) * w;
                        float v1 = (c[ma][nb][half * 2 + 1] + Bias[e * 1024 + cn + 1]) * w;
                        atomicAdd(&Out[(size_t)tok * DM + cn],     v0);
                        atomicAdd(&Out[(size_t)tok * DM + cn + 1], v1);
                    }
                }
            }
        }
    }
}

// -------------------- launch -----------------------------------------------
extern "C" void kernel_launch(void* const* d_in, const int* in_sizes, int n_in,
                              void* d_out, int out_size) {
    const float* x  = (const float*)d_in[0];
    const float* gw = (const float*)d_in[1];
    const float* gb = (const float*)d_in[2];
    const float* w1 = (const float*)d_in[3];
    const float* b1 = (const float*)d_in[4];
    const float* w2 = (const float*)d_in[5];
    const float* b2 = (const float*)d_in[6];
    float* out = (float*)d_out;

    k_init<<<512, 256>>>(out);
    k_gate<<<NT / 8, 256>>>(x, gw, gb);
    k_prefix<<<1, 128>>>();
    k_scatter<<<NT * 2 / 256, 256>>>();
    dim3 gg(MAX_TILES, DM / BN);
    k_gemm<1><<<gg, 256>>>(x, w1, b1, nullptr);
    k_gemm<2><<<gg, 256>>>(nullptr, w2, b2, out);
}

// round 3
// speedup vs baseline: 1.6387x; 1.6387x over previous
#include <cuda_runtime.h>
#include <cstdint>
#include <cstddef>

#define NT        32768                 // tokens = B*T
#define DM        1024
#define NE        8
#define ROWS_MAX  (2*NT + NE*128)       // 66560
#define MAX_TILES (ROWS_MAX/128)        // 520
#define STG       32768                 // per-stage: A 16KB + B 16KB
#define NSTAGE    4
#define SMEM_TOTAL (1024 + NSTAGE*STG)  // 132 KB

// -------------------- device scratch (static, no allocs) --------------------
__device__ int      g_count[NE];
__device__ int      g_cursor[NE];
__device__ int      g_base[NE+1];
__device__ int      g_tileExpert[MAX_TILES];
__device__ int      g_rowToken[ROWS_MAX];
__device__ float    g_rowWeight[ROWS_MAX];
__device__ int      g_tokE[NT*2];
__device__ float    g_tokS[NT*2];
__device__ uint32_t g_xt[(size_t)NT * DM];         // x in tf32 bits
__device__ uint32_t g_hx[(size_t)ROWS_MAX * DM];   // h in tf32 bits
__device__ uint32_t g_w1t[(size_t)NE * DM * DM];   // w1^T tf32 [e][n][k]
__device__ uint32_t g_w2t[(size_t)NE * DM * DM];   // w2^T tf32 [e][n][k]

// -------------------- helpers ----------------------------------------------
__device__ __forceinline__ uint32_t smem_u32(const void* p) {
    uint32_t a;
    asm("{ .reg .u64 t; cvta.to.shared.u64 t, %1; cvt.u32.u64 %0, t; }" : "=r"(a) : "l"(p));
    return a;
}
__device__ __forceinline__ uint32_t f2tf(float f) {
    uint32_t r; asm("cvt.rna.tf32.f32 %0, %1;" : "=r"(r) : "f"(f)); return r;
}
__device__ __forceinline__ void cp16(uint32_t dst, const void* src, uint32_t sz) {
    asm volatile("cp.async.cg.shared.global [%0], [%1], 16, %2;"
                 :: "r"(dst), "l"(src), "r"(sz) : "memory");
}
__device__ __forceinline__ void cp_commit() { asm volatile("cp.async.commit_group;" ::: "memory"); }
__device__ __forceinline__ void cp_wait2()  { asm volatile("cp.async.wait_group 2;"  ::: "memory"); }
__device__ __forceinline__ void mma8(float* c, const uint32_t* a, const uint32_t* b) {
    asm volatile("mma.sync.aligned.m16n8k8.row.col.f32.tf32.tf32.f32 "
                 "{%0,%1,%2,%3}, {%4,%5,%6,%7}, {%8,%9}, {%0,%1,%2,%3};"
                 : "+f"(c[0]), "+f"(c[1]), "+f"(c[2]), "+f"(c[3])
                 : "r"(a[0]), "r"(a[1]), "r"(a[2]), "r"(a[3]),
                   "r"(b[0]), "r"(b[1]));
}

// -------------------- init --------------------------------------------------
__global__ void k_init(float* __restrict__ out) {
    int i = blockIdx.x * blockDim.x + threadIdx.x;
    int nth = gridDim.x * blockDim.x;
    if (i < NE) g_count[i] = 0;
    for (int j = i; j < ROWS_MAX; j += nth) { g_rowToken[j] = -1; g_rowWeight[j] = 0.f; }
    float4 z = make_float4(0.f, 0.f, 0.f, 0.f);
    float4* o4 = (float4*)out;
    int n4 = NT * DM / 4;
    for (int j = i; j < n4; j += nth) o4[j] = z;
}

// -------------------- x -> tf32 --------------------------------------------
__global__ void k_cvtx(const float* __restrict__ x) {
    size_t i = blockIdx.x * blockDim.x + threadIdx.x;
    size_t nth = (size_t)gridDim.x * blockDim.x;
    size_t n4 = (size_t)NT * DM / 4;
    for (size_t j = i; j < n4; j += nth) {
        float4 v = ((const float4*)x)[j];
        uint4 t;
        t.x = f2tf(v.x); t.y = f2tf(v.y); t.z = f2tf(v.z); t.w = f2tf(v.w);
        ((uint4*)g_xt)[j] = t;
    }
}

// -------------------- w[e][k][n] -> wt[e][n][k] (tf32) ----------------------
__global__ void k_transpose(const float* __restrict__ W, int which) {
    __shared__ uint32_t t[32][33];
    uint32_t* WT = which ? g_w2t : g_w1t;
    int e = blockIdx.z;
    int k0 = blockIdx.x * 32, n0 = blockIdx.y * 32;
    const float* w = W + (size_t)e * DM * DM;
    uint32_t* wt = WT + (size_t)e * DM * DM;
    for (int r = threadIdx.y; r < 32; r += 8)
        t[r][threadIdx.x] = f2tf(w[(size_t)(k0 + r) * DM + n0 + threadIdx.x]);
    __syncthreads();
    for (int r = threadIdx.y; r < 32; r += 8)
        wt[(size_t)(n0 + r) * DM + k0 + threadIdx.x] = t[threadIdx.x][r];
}

// -------------------- gating ------------------------------------------------
__global__ void k_gate(const float* __restrict__ x,
                       const float* __restrict__ gw,
                       const float* __restrict__ gb) {
    int warp = (blockIdx.x * blockDim.x + threadIdx.x) >> 5;
    int lane = threadIdx.x & 31;
    if (warp >= NT) return;
    const float* xr = x + (size_t)warp * DM;
    float acc[NE];
#pragma unroll
    for (int e = 0; e < NE; e++) acc[e] = 0.f;
    for (int k = lane; k < DM; k += 32) {
        float xv = xr[k];
#pragma unroll
        for (int e = 0; e < NE; e++) acc[e] += xv * gw[k * NE + e];
    }
#pragma unroll
    for (int e = 0; e < NE; e++)
#pragma unroll
        for (int off = 16; off; off >>= 1)
            acc[e] += __shfl_xor_sync(0xffffffffu, acc[e], off);
    if (lane == 0) {
#pragma unroll
        for (int e = 0; e < NE; e++) acc[e] += gb[e];
        int e0 = 0; float s0 = acc[0];
#pragma unroll
        for (int e = 1; e < NE; e++) if (acc[e] > s0) { s0 = acc[e]; e0 = e; }
        int e1 = -1; float s1 = -3.4e38f;
#pragma unroll
        for (int e = 0; e < NE; e++) if (e != e0 && acc[e] > s1) { s1 = acc[e]; e1 = e; }
        g_tokE[2*warp]   = e0;  g_tokS[2*warp]   = s0;
        g_tokE[2*warp+1] = e1;  g_tokS[2*warp+1] = s1;
        atomicAdd(&g_count[e0], 1);
        atomicAdd(&g_count[e1], 1);
    }
}

// -------------------- prefix (128-aligned) + tile->expert -------------------
__global__ void k_prefix() {
    if (threadIdx.x == 0) {
        int b = 0; g_base[0] = 0;
        for (int e = 0; e < NE; e++) {
            g_cursor[e] = b;
            b += ((g_count[e] + 127) >> 7) << 7;
            g_base[e+1] = b;
        }
    }
    __syncthreads();
    for (int t = threadIdx.x; t < MAX_TILES; t += blockDim.x) {
        int r = t << 7;
        int e = -1;
        for (int q = 0; q < NE; q++)
            if (r >= g_base[q] && r < g_base[q+1]) e = q;
        g_tileExpert[t] = e;
    }
}

__global__ void k_scatter() {
    int i = blockIdx.x * blockDim.x + threadIdx.x;
    if (i >= NT * 2) return;
    int e = g_tokE[i];
    int p = atomicAdd(&g_cursor[e], 1);
    g_rowToken[p]  = i >> 1;
    g_rowWeight[p] = g_tokS[i];
}

// -------------------- pipelined tf32 grouped GEMM ---------------------------
// CTA 128x128, BK=32, 8 warps (2x4), warp tile 64x32, 4-stage cp.async.
template<int PHASE>
__global__ void __launch_bounds__(256, 1)
k_gemm(const float* __restrict__ Bias, float* __restrict__ Out) {
    extern __shared__ char smem[];
    int e = g_tileExpert[blockIdx.x];
    if (e < 0) return;
    const int rowBase = blockIdx.x * 128, colBase = blockIdx.y * 128;
    const int tid = threadIdx.x, lane = tid & 31, wid = tid >> 5;

    float* sBias = (float*)smem;
    if (tid < 128) sBias[tid] = Bias[e * DM + colBase + tid];

    const uint32_t sb = smem_u32(smem) + 1024;

    // ---- producer addressing: thread copies 4 A-chunks + 4 B-chunks / iter
    const int tr = tid >> 3, ch = tid & 7;
    const char* aSrc[4]; uint32_t aSz[4]; uint32_t dOff[4]; const char* bSrc[4];
    const uint32_t* wT = (PHASE == 1 ? g_w1t : g_w2t) + ((size_t)e << 20);
#pragma unroll
    for (int i = 0; i < 4; i++) {
        int row = tr + 32 * i;
        dOff[i] = row * 128 + ((ch * 16) ^ ((row & 7) << 4));
        if (PHASE == 1) {
            int tok = g_rowToken[rowBase + row];
            aSrc[i] = (const char*)(g_xt + (size_t)(tok < 0 ? 0 : tok) * DM) + ch * 16;
            aSz[i]  = (tok < 0) ? 0u : 16u;
        } else {
            aSrc[i] = (const char*)(g_hx + (size_t)(rowBase + row) * DM) + ch * 16;
            aSz[i]  = 16u;
        }
        bSrc[i] = (const char*)(wT + (size_t)(colBase + row) * DM) + ch * 16;
    }

    // ---- prologue: fill 3 stages
#pragma unroll
    for (int p = 0; p < 3; p++) {
        uint32_t base = sb + p * STG;
        int kB = p * 128;
#pragma unroll
        for (int i = 0; i < 4; i++) {
            cp16(base + dOff[i],         aSrc[i] + kB, aSz[i]);
            cp16(base + 16384 + dOff[i], bSrc[i] + kB, 16);
        }
        cp_commit();
    }

    // ---- consumer addressing
    const int g = lane >> 2, tig = lane & 3;
    const int warpM = wid >> 2, warpN = wid & 3;
    const uint32_t gx = (uint32_t)g << 4;
    uint32_t rowA[4], rowB[4];
#pragma unroll
    for (int ma = 0; ma < 4; ma++) rowA[ma] = (warpM * 64 + ma * 16 + g) * 128;
#pragma unroll
    for (int nb = 0; nb < 4; nb++) rowB[nb] = 16384 + (warpN * 32 + nb * 8 + g) * 128;

    float c[4][4][4];
#pragma unroll
    for (int i = 0; i < 4; i++)
#pragma unroll
        for (int j = 0; j < 4; j++)
#pragma unroll
            for (int q = 0; q < 4; q++) c[i][j][q] = 0.f;

    uint32_t af[2][16], bf[2][8];

    for (int kk = 0; kk < 32; kk++) {
        cp_wait2();
        __syncthreads();
        if (kk + 3 < 32) {
            uint32_t base = sb + ((kk + 3) & 3) * STG;
            int kB = (kk + 3) * 128;
#pragma unroll
            for (int i = 0; i < 4; i++) {
                cp16(base + dOff[i],         aSrc[i] + kB, aSz[i]);
                cp16(base + 16384 + dOff[i], bSrc[i] + kB, 16);
            }
        }
        cp_commit();   // empty group in tail keeps wait_group<2> semantics uniform

        const char* stg = smem + 1024 + (kk & 3) * STG;
#define LOADFRAG(K8, A, B)                                                      \
        {                                                                       \
            uint32_t kc  = (((uint32_t)((K8) + tig))     << 2) ^ gx;            \
            uint32_t kc4 = (((uint32_t)((K8) + tig + 4)) << 2) ^ gx;            \
            _Pragma("unroll")                                                   \
            for (int ma = 0; ma < 4; ma++) {                                    \
                (A)[ma*4+0] = *(const uint32_t*)(stg + rowA[ma] + kc);          \
                (A)[ma*4+1] = *(const uint32_t*)(stg + rowA[ma] + 1024 + kc);   \
                (A)[ma*4+2] = *(const uint32_t*)(stg + rowA[ma] + kc4);         \
                (A)[ma*4+3] = *(const uint32_t*)(stg + rowA[ma] + 1024 + kc4);  \
            }                                                                   \
            _Pragma("unroll")                                                   \
            for (int nb = 0; nb < 4; nb++) {                                    \
                (B)[nb*2+0] = *(const uint32_t*)(stg + rowB[nb] + kc);          \
                (B)[nb*2+1] = *(const uint32_t*)(stg + rowB[nb] + kc4);         \
            }                                                                   \
        }
        LOADFRAG(0, af[0], bf[0]);
#pragma unroll
        for (int st = 0; st < 4; st++) {
            if (st < 3) LOADFRAG((st + 1) * 8, af[(st + 1) & 1], bf[(st + 1) & 1]);
            const uint32_t* a = af[st & 1];
            const uint32_t* b = bf[st & 1];
#pragma unroll
            for (int ma = 0; ma < 4; ma++)
#pragma unroll
                for (int nb = 0; nb < 4; nb++)
                    mma8(c[ma][nb], a + ma * 4, b + nb * 2);
        }
#undef LOADFRAG
    }

    // ---- epilogue
#pragma unroll
    for (int ma = 0; ma < 4; ma++) {
#pragma unroll
        for (int half = 0; half < 2; half++) {
            int grow = rowBase + warpM * 64 + ma * 16 + g + half * 8;
            if (PHASE == 1) {
                uint32_t* hrow = g_hx + (size_t)grow * DM + colBase;
#pragma unroll
                for (int nb = 0; nb < 4; nb++) {
                    int cn = warpN * 32 + nb * 8 + tig * 2;
                    float v0 = c[ma][nb][half*2+0] + sBias[cn];
                    float v1 = c[ma][nb][half*2+1] + sBias[cn+1];
                    v0 = fmaxf(v0, 0.f); v1 = fmaxf(v1, 0.f);
                    uint2 u; u.x = f2tf(v0); u.y = f2tf(v1);
                    *(uint2*)(hrow + cn) = u;
                }
            } else {
                int tok = g_rowToken[grow];
                if (tok >= 0) {
                    float w = g_rowWeight[grow];
                    float* orow = Out + (size_t)tok * DM + colBase;
#pragma unroll
                    for (int nb = 0; nb < 4; nb++) {
                        int cn = warpN * 32 + nb * 8 + tig * 2;
                        float v0 = (c[ma][nb][half*2+0] + sBias[cn])   * w;
                        float v1 = (c[ma][nb][half*2+1] + sBias[cn+1]) * w;
                        asm volatile("red.global.add.v2.f32 [%0], {%1,%2};"
                                     :: "l"(orow + cn), "f"(v0), "f"(v1) : "memory");
                    }
                }
            }
        }
    }
}

// -------------------- launch -----------------------------------------------
extern "C" void kernel_launch(void* const* d_in, const int* in_sizes, int n_in,
                              void* d_out, int out_size) {
    const float* x  = (const float*)d_in[0];
    const float* gw = (const float*)d_in[1];
    const float* gb = (const float*)d_in[2];
    const float* w1 = (const float*)d_in[3];
    const float* b1 = (const float*)d_in[4];
    const float* w2 = (const float*)d_in[5];
    const float* b2 = (const float*)d_in[6];
    float* out = (float*)d_out;

    static int smemSet = 0;
    if (!smemSet) {
        cudaFuncSetAttribute(k_gemm<1>, cudaFuncAttributeMaxDynamicSharedMemorySize, SMEM_TOTAL);
        cudaFuncSetAttribute(k_gemm<2>, cudaFuncAttributeMaxDynamicSharedMemorySize, SMEM_TOTAL);
        smemSet = 1;
    }

    k_init<<<512, 256>>>(out);
    k_cvtx<<<1024, 256>>>(x);
    k_transpose<<<dim3(32, 32, NE), dim3(32, 8)>>>(w1, 0);
    k_transpose<<<dim3(32, 32, NE), dim3(32, 8)>>>(w2, 1);
    k_gate<<<NT / 8, 256>>>(x, gw, gb);
    k_prefix<<<1, 128>>>();
    k_scatter<<<NT * 2 / 256, 256>>>();
    dim3 gg(MAX_TILES, DM / 128);
    k_gemm<1><<<gg, 256, SMEM_TOTAL>>>(b1, nullptr);
    k_gemm<2><<<gg, 256, SMEM_TOTAL>>>(b2, out);
}

// round 4
// speedup vs baseline: 1.8705x; 1.1414x over previous
#include <cuda_runtime.h>
#include <cstdint>
#include <cstddef>

#define NT        32768                 // tokens = B*T
#define DM        1024
#define NE        8
#define ROWS_MAX  (2*NT + NE*128)       // 66560
#define MAX_TILES (ROWS_MAX/128)        // 520
#define STG       49152                 // per-stage: A 16KB + B 32KB
#define NSTAGE    3
#define SMEM_TOTAL (1024 + NSTAGE*STG)  // 145 KB

// -------------------- device scratch (static, no allocs) --------------------
__device__ int      g_count[NE];
__device__ int      g_cursor[NE];
__device__ int      g_base[NE+1];
__device__ int      g_tileExpert[MAX_TILES];
__device__ int      g_rowToken[ROWS_MAX];
__device__ float    g_rowWeight[ROWS_MAX];
__device__ int      g_tokE[NT*2];
__device__ float    g_tokS[NT*2];
__device__ uint32_t g_xt[(size_t)NT * DM];         // x in tf32 bits
__device__ uint32_t g_hx[(size_t)ROWS_MAX * DM];   // h in tf32 bits
__device__ uint32_t g_w1t[(size_t)NE * DM * DM];   // w1^T tf32 [e][n][k]
__device__ uint32_t g_w2t[(size_t)NE * DM * DM];   // w2^T tf32 [e][n][k]

// -------------------- helpers ----------------------------------------------
__device__ __forceinline__ uint32_t smem_u32(const void* p) {
    uint32_t a;
    asm("{ .reg .u64 t; cvta.to.shared.u64 t, %1; cvt.u32.u64 %0, t; }" : "=r"(a) : "l"(p));
    return a;
}
__device__ __forceinline__ uint32_t f2tf(float f) {
    uint32_t r; asm("cvt.rna.tf32.f32 %0, %1;" : "=r"(r) : "f"(f)); return r;
}
__device__ __forceinline__ void cp16(uint32_t dst, const void* src, uint32_t sz) {
    asm volatile("cp.async.cg.shared.global [%0], [%1], 16, %2;"
                 :: "r"(dst), "l"(src), "r"(sz) : "memory");
}
__device__ __forceinline__ void cp_commit() { asm volatile("cp.async.commit_group;" ::: "memory"); }
__device__ __forceinline__ void cp_wait1()  { asm volatile("cp.async.wait_group 1;"  ::: "memory"); }
__device__ __forceinline__ void mma8(float* c, const uint32_t* a, const uint32_t* b) {
    asm volatile("mma.sync.aligned.m16n8k8.row.col.f32.tf32.tf32.f32 "
                 "{%0,%1,%2,%3}, {%4,%5,%6,%7}, {%8,%9}, {%0,%1,%2,%3};"
                 : "+f"(c[0]), "+f"(c[1]), "+f"(c[2]), "+f"(c[3])
                 : "r"(a[0]), "r"(a[1]), "r"(a[2]), "r"(a[3]),
                   "r"(b[0]), "r"(b[1]));
}

// -------------------- init --------------------------------------------------
__global__ void k_init(float* __restrict__ out) {
    int i = blockIdx.x * blockDim.x + threadIdx.x;
    int nth = gridDim.x * blockDim.x;
    if (i < NE) g_count[i] = 0;
    for (int j = i; j < ROWS_MAX; j += nth) { g_rowToken[j] = -1; g_rowWeight[j] = 0.f; }
    float4 z = make_float4(0.f, 0.f, 0.f, 0.f);
    float4* o4 = (float4*)out;
    int n4 = NT * DM / 4;
    for (int j = i; j < n4; j += nth) o4[j] = z;
}

// -------------------- x -> tf32 --------------------------------------------
__global__ void k_cvtx(const float* __restrict__ x) {
    size_t i = blockIdx.x * blockDim.x + threadIdx.x;
    size_t nth = (size_t)gridDim.x * blockDim.x;
    size_t n4 = (size_t)NT * DM / 4;
    for (size_t j = i; j < n4; j += nth) {
        float4 v = ((const float4*)x)[j];
        uint4 t;
        t.x = f2tf(v.x); t.y = f2tf(v.y); t.z = f2tf(v.z); t.w = f2tf(v.w);
        ((uint4*)g_xt)[j] = t;
    }
}

// -------------------- w[e][k][n] -> wt[e][n][k] (tf32) ----------------------
__global__ void k_transpose(const float* __restrict__ W, int which) {
    __shared__ uint32_t t[32][33];
    uint32_t* WT = which ? g_w2t : g_w1t;
    int e = blockIdx.z;
    int k0 = blockIdx.x * 32, n0 = blockIdx.y * 32;
    const float* w = W + (size_t)e * DM * DM;
    uint32_t* wt = WT + (size_t)e * DM * DM;
    for (int r = threadIdx.y; r < 32; r += 8)
        t[r][threadIdx.x] = f2tf(w[(size_t)(k0 + r) * DM + n0 + threadIdx.x]);
    __syncthreads();
    for (int r = threadIdx.y; r < 32; r += 8)
        wt[(size_t)(n0 + r) * DM + k0 + threadIdx.x] = t[threadIdx.x][r];
}

// -------------------- gating ------------------------------------------------
__global__ void k_gate(const float* __restrict__ x,
                       const float* __restrict__ gw,
                       const float* __restrict__ gb) {
    int warp = (blockIdx.x * blockDim.x + threadIdx.x) >> 5;
    int lane = threadIdx.x & 31;
    if (warp >= NT) return;
    const float* xr = x + (size_t)warp * DM;
    float acc[NE];
#pragma unroll
    for (int e = 0; e < NE; e++) acc[e] = 0.f;
    for (int k = lane; k < DM; k += 32) {
        float xv = xr[k];
#pragma unroll
        for (int e = 0; e < NE; e++) acc[e] += xv * gw[k * NE + e];
    }
#pragma unroll
    for (int e = 0; e < NE; e++)
#pragma unroll
        for (int off = 16; off; off >>= 1)
            acc[e] += __shfl_xor_sync(0xffffffffu, acc[e], off);
    if (lane == 0) {
#pragma unroll
        for (int e = 0; e < NE; e++) acc[e] += gb[e];
        int e0 = 0; float s0 = acc[0];
#pragma unroll
        for (int e = 1; e < NE; e++) if (acc[e] > s0) { s0 = acc[e]; e0 = e; }
        int e1 = -1; float s1 = -3.4e38f;
#pragma unroll
        for (int e = 0; e < NE; e++) if (e != e0 && acc[e] > s1) { s1 = acc[e]; e1 = e; }
        g_tokE[2*warp]   = e0;  g_tokS[2*warp]   = s0;
        g_tokE[2*warp+1] = e1;  g_tokS[2*warp+1] = s1;
        atomicAdd(&g_count[e0], 1);
        atomicAdd(&g_count[e1], 1);
    }
}

// -------------------- prefix (128-aligned) + tile->expert -------------------
__global__ void k_prefix() {
    if (threadIdx.x == 0) {
        int b = 0; g_base[0] = 0;
        for (int e = 0; e < NE; e++) {
            g_cursor[e] = b;
            b += ((g_count[e] + 127) >> 7) << 7;
            g_base[e+1] = b;
        }
    }
    __syncthreads();
    for (int t = threadIdx.x; t < MAX_TILES; t += blockDim.x) {
        int r = t << 7;
        int e = -1;
        for (int q = 0; q < NE; q++)
            if (r >= g_base[q] && r < g_base[q+1]) e = q;
        g_tileExpert[t] = e;
    }
}

__global__ void k_scatter() {
    int i = blockIdx.x * blockDim.x + threadIdx.x;
    if (i >= NT * 2) return;
    int e = g_tokE[i];
    int p = atomicAdd(&g_cursor[e], 1);
    g_rowToken[p]  = i >> 1;
    g_rowWeight[p] = g_tokS[i];
}

// -------------------- pipelined tf32 grouped GEMM ---------------------------
// CTA 128x256, BK=32, 8 warps (2x4), warp tile 64x64, 3-stage cp.async.
template<int PHASE>
__global__ void __launch_bounds__(256, 1)
k_gemm(const float* __restrict__ Bias, float* __restrict__ Out) {
    extern __shared__ char smem[];
    int e = g_tileExpert[blockIdx.x];
    if (e < 0) return;
    const int rowBase = blockIdx.x * 128, colBase = blockIdx.y * 256;
    const int tid = threadIdx.x, lane = tid & 31, wid = tid >> 5;

    float* sBias = (float*)smem;
    sBias[tid] = Bias[e * DM + colBase + tid];

    const uint32_t sb = smem_u32(smem) + 1024;

    // ---- producer addressing: 4 A-chunks + 8 B-chunks per thread per iter
    const int tr = tid >> 3, ch = tid & 7;                 // tr 0..31, ch 0..7
    const uint32_t dOff0 = tr * 128 + ((ch * 16) ^ ((tr & 7) << 4));
    const uint32_t* wT = (PHASE == 1 ? g_w1t : g_w2t) + ((size_t)e << 20);
    const char* bBase = (const char*)(wT + (size_t)(colBase + tr) * DM) + ch * 16;

    const char* aSrc[4]; uint32_t aSz[4];
#pragma unroll
    for (int i = 0; i < 4; i++) {
        int row = tr + 32 * i;
        if (PHASE == 1) {
            int tok = g_rowToken[rowBase + row];
            aSrc[i] = (const char*)(g_xt + (size_t)(tok < 0 ? 0 : tok) * DM) + ch * 16;
            aSz[i]  = (tok < 0) ? 0u : 16u;
        } else {
            aSrc[i] = (const char*)(g_hx + (size_t)(rowBase + row) * DM) + ch * 16;
            aSz[i]  = 16u;
        }
    }

#define PRODUCE(STAGE, KB)                                                      \
    {                                                                           \
        uint32_t base_ = sb + (STAGE) * STG;                                    \
        _Pragma("unroll")                                                       \
        for (int i_ = 0; i_ < 4; i_++)                                          \
            cp16(base_ + dOff0 + i_ * 4096, aSrc[i_] + (KB), aSz[i_]);          \
        _Pragma("unroll")                                                       \
        for (int i_ = 0; i_ < 8; i_++)                                          \
            cp16(base_ + 16384 + dOff0 + i_ * 4096,                             \
                 bBase + (size_t)i_ * (32u * DM * 4u) + (KB), 16);              \
    }

    // ---- prologue: fill 2 stages
    PRODUCE(0, 0);    cp_commit();
    PRODUCE(1, 128);  cp_commit();

    // ---- consumer addressing
    const int g = lane >> 2, tig = lane & 3;
    const int warpM = wid >> 2, warpN = wid & 3;
    const uint32_t gx = (uint32_t)g << 4;
    uint32_t rowA[4], rowB[8];
#pragma unroll
    for (int ma = 0; ma < 4; ma++) rowA[ma] = (warpM * 64 + ma * 16 + g) * 128;
#pragma unroll
    for (int nb = 0; nb < 8; nb++) rowB[nb] = 16384 + (warpN * 64 + nb * 8 + g) * 128;

    float c[4][8][4];
#pragma unroll
    for (int i = 0; i < 4; i++)
#pragma unroll
        for (int j = 0; j < 8; j++)
#pragma unroll
            for (int q = 0; q < 4; q++) c[i][j][q] = 0.f;

    for (int kk = 0; kk < 32; kk++) {
        cp_wait1();
        __syncthreads();
        if (kk + 2 < 32) {
            int s = (kk + 2) % NSTAGE;
            int kB = (kk + 2) * 128;
            PRODUCE(s, kB);
        }
        cp_commit();   // empty group in tail keeps wait_group<1> counting uniform

        const char* stg = smem + 1024 + (kk % NSTAGE) * STG;
#pragma unroll
        for (int k8 = 0; k8 < 4; k8++) {
            uint32_t kc  = (((uint32_t)(k8 * 8 + tig))     << 2) ^ gx;
            uint32_t kc4 = (((uint32_t)(k8 * 8 + tig + 4)) << 2) ^ gx;
            uint32_t a[16], b[16];
#pragma unroll
            for (int ma = 0; ma < 4; ma++) {
                a[ma*4+0] = *(const uint32_t*)(stg + rowA[ma] + kc);
                a[ma*4+1] = *(const uint32_t*)(stg + rowA[ma] + 1024 + kc);
                a[ma*4+2] = *(const uint32_t*)(stg + rowA[ma] + kc4);
                a[ma*4+3] = *(const uint32_t*)(stg + rowA[ma] + 1024 + kc4);
            }
#pragma unroll
            for (int nb = 0; nb < 8; nb++) {
                b[nb*2+0] = *(const uint32_t*)(stg + rowB[nb] + kc);
                b[nb*2+1] = *(const uint32_t*)(stg + rowB[nb] + kc4);
            }
#pragma unroll
            for (int ma = 0; ma < 4; ma++)
#pragma unroll
                for (int nb = 0; nb < 8; nb++)
                    mma8(c[ma][nb], a + ma * 4, b + nb * 2);
        }
    }
#undef PRODUCE

    // ---- epilogue
#pragma unroll
    for (int ma = 0; ma < 4; ma++) {
#pragma unroll
        for (int half = 0; half < 2; half++) {
            int grow = rowBase + warpM * 64 + ma * 16 + g + half * 8;
            if (PHASE == 1) {
                uint32_t* hrow = g_hx + (size_t)grow * DM + colBase;
#pragma unroll
                for (int nb = 0; nb < 8; nb++) {
                    int cn = warpN * 64 + nb * 8 + tig * 2;
                    float v0 = c[ma][nb][half*2+0] + sBias[cn];
                    float v1 = c[ma][nb][half*2+1] + sBias[cn+1];
                    v0 = fmaxf(v0, 0.f); v1 = fmaxf(v1, 0.f);
                    uint2 u; u.x = f2tf(v0); u.y = f2tf(v1);
                    *(uint2*)(hrow + cn) = u;
                }
            } else {
                int tok = g_rowToken[grow];
                if (tok >= 0) {
                    float w = g_rowWeight[grow];
                    float* orow = Out + (size_t)tok * DM + colBase;
#pragma unroll
                    for (int nb = 0; nb < 8; nb++) {
                        int cn = warpN * 64 + nb * 8 + tig * 2;
                        float v0 = (c[ma][nb][half*2+0] + sBias[cn])   * w;
                        float v1 = (c[ma][nb][half*2+1] + sBias[cn+1]) * w;
                        asm volatile("red.global.add.v2.f32 [%0], {%1,%2};"
                                     :: "l"(orow + cn), "f"(v0), "f"(v1) : "memory");
                    }
                }
            }
        }
    }
}

// -------------------- launch -----------------------------------------------
extern "C" void kernel_launch(void* const* d_in, const int* in_sizes, int n_in,
                              void* d_out, int out_size) {
    const float* x  = (const float*)d_in[0];
    const float* gw = (const float*)d_in[1];
    const float* gb = (const float*)d_in[2];
    const float* w1 = (const float*)d_in[3];
    const float* b1 = (const float*)d_in[4];
    const float* w2 = (const float*)d_in[5];
    const float* b2 = (const float*)d_in[6];
    float* out = (float*)d_out;

    static int smemSet = 0;
    if (!smemSet) {
        cudaFuncSetAttribute(k_gemm<1>, cudaFuncAttributeMaxDynamicSharedMemorySize, SMEM_TOTAL);
        cudaFuncSetAttribute(k_gemm<2>, cudaFuncAttributeMaxDynamicSharedMemorySize, SMEM_TOTAL);
        smemSet = 1;
    }

    k_init<<<512, 256>>>(out);
    k_cvtx<<<1024, 256>>>(x);
    k_transpose<<<dim3(32, 32, NE), dim3(32, 8)>>>(w1, 0);
    k_transpose<<<dim3(32, 32, NE), dim3(32, 8)>>>(w2, 1);
    k_gate<<<NT / 8, 256>>>(x, gw, gb);
    k_prefix<<<1, 128>>>();
    k_scatter<<<NT * 2 / 256, 256>>>();
    dim3 gg(MAX_TILES, DM / 256);
    k_gemm<1><<<gg, 256, SMEM_TOTAL>>>(b1, nullptr);
    k_gemm<2><<<gg, 256, SMEM_TOTAL>>>(b2, out);
}

// round 5
// speedup vs baseline: 2.1176x; 1.1321x over previous
#include <cuda_runtime.h>
#include <cstdint>
#include <cstddef>

#define NT        32768                 // tokens = B*T
#define DM        1024
#define NE        8
#define ROWS_MAX  (2*NT + NE*128)       // 66560
#define MAX_TILES (ROWS_MAX/128)        // 520
#define STG       32768                 // per-stage: A 16KB + B 16KB
#define NSTAGE    3
#define SMEM_TOTAL (1024 + NSTAGE*STG)  // ~97 KB -> 2 CTAs/SM

// -------------------- device scratch (static, no allocs) --------------------
__device__ int      g_count[NE];
__device__ int      g_cursor[NE];
__device__ int      g_base[NE+1];
__device__ int      g_tileExpert[MAX_TILES];
__device__ int      g_rowToken[ROWS_MAX];
__device__ float    g_rowWeight[ROWS_MAX];
__device__ int      g_tokE[NT*2];
__device__ float    g_tokS[NT*2];
__device__ uint32_t g_xt[(size_t)NT * DM];         // x in tf32 bits
__device__ uint32_t g_hx[(size_t)ROWS_MAX * DM];   // h in tf32 bits
__device__ uint32_t g_w1t[(size_t)NE * DM * DM];   // w1^T tf32 [e][n][k]
__device__ uint32_t g_w2t[(size_t)NE * DM * DM];   // w2^T tf32 [e][n][k]

// -------------------- helpers ----------------------------------------------
__device__ __forceinline__ uint32_t smem_u32(const void* p) {
    uint32_t a;
    asm("{ .reg .u64 t; cvta.to.shared.u64 t, %1; cvt.u32.u64 %0, t; }" : "=r"(a) : "l"(p));
    return a;
}
__device__ __forceinline__ uint32_t f2tf(float f) {
    uint32_t r; asm("cvt.rna.tf32.f32 %0, %1;" : "=r"(r) : "f"(f)); return r;
}
__device__ __forceinline__ void cp16(uint32_t dst, const void* src, uint32_t sz) {
    asm volatile("cp.async.cg.shared.global [%0], [%1], 16, %2;"
                 :: "r"(dst), "l"(src), "r"(sz) : "memory");
}
__device__ __forceinline__ void cp_commit() { asm volatile("cp.async.commit_group;" ::: "memory"); }
__device__ __forceinline__ void cp_wait1()  { asm volatile("cp.async.wait_group 1;"  ::: "memory"); }
__device__ __forceinline__ void ldsm4(uint32_t* r, uint32_t addr) {
    asm volatile("ldmatrix.sync.aligned.m8n8.x4.shared.b16 {%0,%1,%2,%3}, [%4];"
                 : "=r"(r[0]), "=r"(r[1]), "=r"(r[2]), "=r"(r[3]) : "r"(addr));
}
__device__ __forceinline__ void mma8(float* c, const uint32_t* a, const uint32_t* b) {
    asm volatile("mma.sync.aligned.m16n8k8.row.col.f32.tf32.tf32.f32 "
                 "{%0,%1,%2,%3}, {%4,%5,%6,%7}, {%8,%9}, {%0,%1,%2,%3};"
                 : "+f"(c[0]), "+f"(c[1]), "+f"(c[2]), "+f"(c[3])
                 : "r"(a[0]), "r"(a[1]), "r"(a[2]), "r"(a[3]),
                   "r"(b[0]), "r"(b[1]));
}

// -------------------- init --------------------------------------------------
__global__ void k_init(float* __restrict__ out) {
    int i = blockIdx.x * blockDim.x + threadIdx.x;
    int nth = gridDim.x * blockDim.x;
    if (i < NE) g_count[i] = 0;
    for (int j = i; j < ROWS_MAX; j += nth) { g_rowToken[j] = -1; g_rowWeight[j] = 0.f; }
    float4 z = make_float4(0.f, 0.f, 0.f, 0.f);
    float4* o4 = (float4*)out;
    int n4 = NT * DM / 4;
    for (int j = i; j < n4; j += nth) o4[j] = z;
}

// -------------------- x -> tf32 --------------------------------------------
__global__ void k_cvtx(const float* __restrict__ x) {
    size_t i = blockIdx.x * blockDim.x + threadIdx.x;
    size_t nth = (size_t)gridDim.x * blockDim.x;
    size_t n4 = (size_t)NT * DM / 4;
    for (size_t j = i; j < n4; j += nth) {
        float4 v = ((const float4*)x)[j];
        uint4 t;
        t.x = f2tf(v.x); t.y = f2tf(v.y); t.z = f2tf(v.z); t.w = f2tf(v.w);
        ((uint4*)g_xt)[j] = t;
    }
}

// -------------------- w[e][k][n] -> wt[e][n][k] (tf32) ----------------------
__global__ void k_transpose(const float* __restrict__ W, int which) {
    __shared__ uint32_t t[32][33];
    uint32_t* WT = which ? g_w2t : g_w1t;
    int e = blockIdx.z;
    int k0 = blockIdx.x * 32, n0 = blockIdx.y * 32;
    const float* w = W + (size_t)e * DM * DM;
    uint32_t* wt = WT + (size_t)e * DM * DM;
    for (int r = threadIdx.y; r < 32; r += 8)
        t[r][threadIdx.x] = f2tf(w[(size_t)(k0 + r) * DM + n0 + threadIdx.x]);
    __syncthreads();
    for (int r = threadIdx.y; r < 32; r += 8)
        wt[(size_t)(n0 + r) * DM + k0 + threadIdx.x] = t[threadIdx.x][r];
}

// -------------------- gating ------------------------------------------------
__global__ void k_gate(const float* __restrict__ x,
                       const float* __restrict__ gw,
                       const float* __restrict__ gb) {
    int warp = (blockIdx.x * blockDim.x + threadIdx.x) >> 5;
    int lane = threadIdx.x & 31;
    if (warp >= NT) return;
    const float* xr = x + (size_t)warp * DM;
    float acc[NE];
#pragma unroll
    for (int e = 0; e < NE; e++) acc[e] = 0.f;
    for (int k = lane; k < DM; k += 32) {
        float xv = xr[k];
#pragma unroll
        for (int e = 0; e < NE; e++) acc[e] += xv * gw[k * NE + e];
    }
#pragma unroll
    for (int e = 0; e < NE; e++)
#pragma unroll
        for (int off = 16; off; off >>= 1)
            acc[e] += __shfl_xor_sync(0xffffffffu, acc[e], off);
    if (lane == 0) {
#pragma unroll
        for (int e = 0; e < NE; e++) acc[e] += gb[e];
        int e0 = 0; float s0 = acc[0];
#pragma unroll
        for (int e = 1; e < NE; e++) if (acc[e] > s0) { s0 = acc[e]; e0 = e; }
        int e1 = -1; float s1 = -3.4e38f;
#pragma unroll
        for (int e = 0; e < NE; e++) if (e != e0 && acc[e] > s1) { s1 = acc[e]; e1 = e; }
        g_tokE[2*warp]   = e0;  g_tokS[2*warp]   = s0;
        g_tokE[2*warp+1] = e1;  g_tokS[2*warp+1] = s1;
        atomicAdd(&g_count[e0], 1);
        atomicAdd(&g_count[e1], 1);
    }
}

// -------------------- prefix (128-aligned) + tile->expert -------------------
__global__ void k_prefix() {
    if (threadIdx.x == 0) {
        int b = 0; g_base[0] = 0;
        for (int e = 0; e < NE; e++) {
            g_cursor[e] = b;
            b += ((g_count[e] + 127) >> 7) << 7;
            g_base[e+1] = b;
        }
    }
    __syncthreads();
    for (int t = threadIdx.x; t < MAX_TILES; t += blockDim.x) {
        int r = t << 7;
        int e = -1;
        for (int q = 0; q < NE; q++)
            if (r >= g_base[q] && r < g_base[q+1]) e = q;
        g_tileExpert[t] = e;
    }
}

__global__ void k_scatter() {
    int i = blockIdx.x * blockDim.x + threadIdx.x;
    if (i >= NT * 2) return;
    int e = g_tokE[i];
    int p = atomicAdd(&g_cursor[e], 1);
    g_rowToken[p]  = i >> 1;
    g_rowWeight[p] = g_tokS[i];
}

// -------------------- pipelined tf32 grouped GEMM ---------------------------
// CTA 128x128, 128 threads (4 warps 2x2, warp tile 64x64), BK=32, 3-stage
// cp.async, ldmatrix fragment loads, 2 CTAs/SM.
template<int PHASE>
__global__ void __launch_bounds__(128, 2)
k_gemm(const float* __restrict__ Bias, float* __restrict__ Out) {
    extern __shared__ char smem[];
    int e = g_tileExpert[blockIdx.x];
    if (e < 0) return;
    const int rowBase = blockIdx.x * 128, colBase = blockIdx.y * 128;
    const int tid = threadIdx.x, lane = tid & 31, wid = tid >> 5;

    float* sBias = (float*)smem;
    sBias[tid] = Bias[e * DM + colBase + tid];

    const uint32_t sb = smem_u32(smem) + 1024;

    // ---- producer: 8 A-chunks + 8 B-chunks (16B) per thread per stage ----
    const int tr = tid >> 3, ch = tid & 7;                 // tr 0..15, ch 0..7
    // swizzle term depends only on (row&7) == (tr&7): invariant across i*16 rows
    const uint32_t dOff0 = tr * 128 + ((ch * 16) ^ ((tr & 7) << 4));
    const char* wT = (const char*)((PHASE == 1 ? g_w1t : g_w2t) + ((size_t)e << 20));
    const char* aBase = (PHASE == 1) ? (const char*)g_xt
                                     : (const char*)(g_hx + (size_t)rowBase * DM);
    uint32_t aOff[8], aSz[8], bOff[8];
#pragma unroll
    for (int i = 0; i < 8; i++) {
        int row = tr + 16 * i;
        if (PHASE == 1) {
            int tok = g_rowToken[rowBase + row];
            aOff[i] = (uint32_t)(tok < 0 ? 0 : tok) * 4096u + ch * 16;
            aSz[i]  = (tok < 0) ? 0u : 16u;
        } else {
            aOff[i] = (uint32_t)row * 4096u + ch * 16;
            aSz[i]  = 16u;
        }
        bOff[i] = (uint32_t)(colBase + row) * 4096u + ch * 16;
    }

#define PRODUCE(STAGE, KB)                                                      \
    {                                                                           \
        uint32_t base_ = sb + (STAGE) * STG;                                    \
        _Pragma("unroll")                                                       \
        for (int i_ = 0; i_ < 8; i_++) {                                        \
            cp16(base_ + dOff0 + i_ * 2048,         aBase + aOff[i_] + (KB), aSz[i_]); \
            cp16(base_ + 16384 + dOff0 + i_ * 2048, wT + bOff[i_] + (KB), 16); \
        }                                                                       \
    }

    PRODUCE(0, 0);    cp_commit();
    PRODUCE(1, 128);  cp_commit();

    // ---- consumer: ldmatrix addressing ----
    const int g = lane >> 2, tig = lane & 3;
    const int warpM = wid >> 1, warpN = wid & 1;
    const int lm = lane >> 3, lj = lane & 7;       // matrix idx, row within matrix
    const uint32_t swzMask = (uint32_t)lj << 4;
    const uint32_t aHalf = (uint32_t)(lm >> 1) << 4;   // A: m0,m1 half0; m2,m3 half1
    const uint32_t bHalf = (uint32_t)(lm & 1) << 4;    // B: m0,m2 half0; m1,m3 half1
    uint32_t aRow[4], bRow[4];
#pragma unroll
    for (int ma = 0; ma < 4; ma++)
        aRow[ma] = (uint32_t)(warpM * 64 + ma * 16 + (lm & 1) * 8 + lj) * 128;
#pragma unroll
    for (int p = 0; p < 4; p++)
        bRow[p] = 16384u + (uint32_t)(warpN * 64 + p * 16 + (lm >> 1) * 8 + lj) * 128;

    float c[4][8][4];
#pragma unroll
    for (int i = 0; i < 4; i++)
#pragma unroll
        for (int j = 0; j < 8; j++)
#pragma unroll
            for (int q = 0; q < 4; q++) c[i][j][q] = 0.f;

    for (int kk = 0; kk < 32; kk++) {
        cp_wait1();
        __syncthreads();
        if (kk + 2 < 32) {
            int s = (kk + 2) % NSTAGE;
            int kB = (kk + 2) * 128;
            PRODUCE(s, kB);
        }
        cp_commit();   // empty group in tail keeps wait_group<1> counting uniform

        const uint32_t stgA = sb + (kk % NSTAGE) * STG;
#pragma unroll
        for (int k8 = 0; k8 < 4; k8++) {
            const uint32_t kterm = (uint32_t)k8 * 32;
            uint32_t a[4][4], b[4][4];
#pragma unroll
            for (int ma = 0; ma < 4; ma++)
                ldsm4(a[ma], stgA + aRow[ma] + ((kterm + aHalf) ^ swzMask));
#pragma unroll
            for (int p = 0; p < 4; p++)
                ldsm4(b[p], stgA + bRow[p] + ((kterm + bHalf) ^ swzMask));
#pragma unroll
            for (int ma = 0; ma < 4; ma++)
#pragma unroll
                for (int nb = 0; nb < 8; nb++)
                    mma8(c[ma][nb], a[ma], &b[nb >> 1][(nb & 1) * 2]);
        }
    }
#undef PRODUCE

    // ---- epilogue ----
#pragma unroll
    for (int ma = 0; ma < 4; ma++) {
#pragma unroll
        for (int half = 0; half < 2; half++) {
            int grow = rowBase + warpM * 64 + ma * 16 + g + half * 8;
            if (PHASE == 1) {
                uint32_t* hrow = g_hx + (size_t)grow * DM + colBase;
#pragma unroll
                for (int nb = 0; nb < 8; nb++) {
                    int cn = warpN * 64 + nb * 8 + tig * 2;
                    float v0 = c[ma][nb][half*2+0] + sBias[cn];
                    float v1 = c[ma][nb][half*2+1] + sBias[cn+1];
                    v0 = fmaxf(v0, 0.f); v1 = fmaxf(v1, 0.f);
                    uint2 u; u.x = f2tf(v0); u.y = f2tf(v1);
                    *(uint2*)(hrow + cn) = u;
                }
            } else {
                int tok = g_rowToken[grow];
                if (tok >= 0) {
                    float w = g_rowWeight[grow];
                    float* orow = Out + (size_t)tok * DM + colBase;
#pragma unroll
                    for (int nb = 0; nb < 8; nb++) {
                        int cn = warpN * 64 + nb * 8 + tig * 2;
                        float v0 = (c[ma][nb][half*2+0] + sBias[cn])   * w;
                        float v1 = (c[ma][nb][half*2+1] + sBias[cn+1]) * w;
                        asm volatile("red.global.add.v2.f32 [%0], {%1,%2};"
                                     :: "l"(orow + cn), "f"(v0), "f"(v1) : "memory");
                    }
                }
            }
        }
    }
}

// -------------------- launch -----------------------------------------------
extern "C" void kernel_launch(void* const* d_in, const int* in_sizes, int n_in,
                              void* d_out, int out_size) {
    const float* x  = (const float*)d_in[0];
    const float* gw = (const float*)d_in[1];
    const float* gb = (const float*)d_in[2];
    const float* w1 = (const float*)d_in[3];
    const float* b1 = (const float*)d_in[4];
    const float* w2 = (const float*)d_in[5];
    const float* b2 = (const float*)d_in[6];
    float* out = (float*)d_out;

    static int smemSet = 0;
    if (!smemSet) {
        cudaFuncSetAttribute(k_gemm<1>, cudaFuncAttributeMaxDynamicSharedMemorySize, SMEM_TOTAL);
        cudaFuncSetAttribute(k_gemm<2>, cudaFuncAttributeMaxDynamicSharedMemorySize, SMEM_TOTAL);
        smemSet = 1;
    }

    k_init<<<512, 256>>>(out);
    k_cvtx<<<1024, 256>>>(x);
    k_transpose<<<dim3(32, 32, NE), dim3(32, 8)>>>(w1, 0);
    k_transpose<<<dim3(32, 32, NE), dim3(32, 8)>>>(w2, 1);
    k_gate<<<NT / 8, 256>>>(x, gw, gb);
    k_prefix<<<1, 128>>>();
    k_scatter<<<NT * 2 / 256, 256>>>();
    dim3 gg(MAX_TILES, DM / 128);
    k_gemm<1><<<gg, 128, SMEM_TOTAL>>>(b1, nullptr);
    k_gemm<2><<<gg, 128, SMEM_TOTAL>>>(b2, out);
}

// round 6
// speedup vs baseline: 2.1963x; 1.0372x over previous
#include <cuda_runtime.h>
#include <cstdint>
#include <cstddef>

#define NT        32768                 // tokens = B*T
#define DM        1024
#define NE        8
#define ROWS_MAX  (2*NT + NE*128)       // 66560
#define MAX_TILES (ROWS_MAX/128)        // 520
#define STG       32768                 // per-stage: A 16KB + B 16KB
#define NSTAGE    3
#define SMEM_TOTAL (1024 + NSTAGE*STG)  // ~97 KB -> 2 CTAs/SM

// -------------------- device scratch (static, no allocs) --------------------
__device__ int      g_count[NE];
__device__ int      g_cursor[NE];
__device__ int      g_base[NE+1];
__device__ int      g_tileExpert[MAX_TILES];
__device__ int      g_rowToken[ROWS_MAX];
__device__ float    g_rowWeight[ROWS_MAX];
__device__ int      g_tokE[NT*2];
__device__ float    g_tokS[NT*2];
__device__ uint32_t g_xt[(size_t)NT * DM];         // x in tf32 bits
__device__ uint32_t g_hx[(size_t)ROWS_MAX * DM];   // h in tf32 bits
__device__ uint32_t g_w1t[(size_t)NE * DM * DM];   // w1^T tf32 [e][n][k]
__device__ uint32_t g_w2t[(size_t)NE * DM * DM];   // w2^T tf32 [e][n][k]

// -------------------- helpers ----------------------------------------------
__device__ __forceinline__ uint32_t smem_u32(const void* p) {
    uint32_t a;
    asm("{ .reg .u64 t; cvta.to.shared.u64 t, %1; cvt.u32.u64 %0, t; }" : "=r"(a) : "l"(p));
    return a;
}
__device__ __forceinline__ uint32_t f2tf(float f) {
    uint32_t r; asm("cvt.rna.tf32.f32 %0, %1;" : "=r"(r) : "f"(f)); return r;
}
__device__ __forceinline__ void cp16(uint32_t dst, const void* src, uint32_t sz) {
    asm volatile("cp.async.cg.shared.global [%0], [%1], 16, %2;"
                 :: "r"(dst), "l"(src), "r"(sz) : "memory");
}
__device__ __forceinline__ void cp_commit() { asm volatile("cp.async.commit_group;" ::: "memory"); }
__device__ __forceinline__ void cp_wait1()  { asm volatile("cp.async.wait_group 1;"  ::: "memory"); }
__device__ __forceinline__ void ldsm4(uint32_t* r, uint32_t addr) {
    asm volatile("ldmatrix.sync.aligned.m8n8.x4.shared.b16 {%0,%1,%2,%3}, [%4];"
                 : "=r"(r[0]), "=r"(r[1]), "=r"(r[2]), "=r"(r[3]) : "r"(addr));
}
__device__ __forceinline__ void mma8(float* c, const uint32_t* a, const uint32_t* b) {
    asm volatile("mma.sync.aligned.m16n8k8.row.col.f32.tf32.tf32.f32 "
                 "{%0,%1,%2,%3}, {%4,%5,%6,%7}, {%8,%9}, {%0,%1,%2,%3};"
                 : "+f"(c[0]), "+f"(c[1]), "+f"(c[2]), "+f"(c[3])
                 : "r"(a[0]), "r"(a[1]), "r"(a[2]), "r"(a[3]),
                   "r"(b[0]), "r"(b[1]));
}

// -------------------- init --------------------------------------------------
__global__ void k_init(float* __restrict__ out) {
    int i = blockIdx.x * blockDim.x + threadIdx.x;
    int nth = gridDim.x * blockDim.x;
    if (i < NE) g_count[i] = 0;
    for (int j = i; j < ROWS_MAX; j += nth) { g_rowToken[j] = -1; g_rowWeight[j] = 0.f; }
    float4 z = make_float4(0.f, 0.f, 0.f, 0.f);
    float4* o4 = (float4*)out;
    int n4 = NT * DM / 4;
    for (int j = i; j < n4; j += nth) o4[j] = z;
}

// -------------------- w[e][k][n] -> wt[e][n][k] (tf32) ----------------------
__global__ void k_transpose(const float* __restrict__ W, int which) {
    __shared__ uint32_t t[32][33];
    uint32_t* WT = which ? g_w2t : g_w1t;
    int e = blockIdx.z;
    int k0 = blockIdx.x * 32, n0 = blockIdx.y * 32;
    const float* w = W + (size_t)e * DM * DM;
    uint32_t* wt = WT + (size_t)e * DM * DM;
    for (int r = threadIdx.y; r < 32; r += 8)
        t[r][threadIdx.x] = f2tf(w[(size_t)(k0 + r) * DM + n0 + threadIdx.x]);
    __syncthreads();
    for (int r = threadIdx.y; r < 32; r += 8)
        wt[(size_t)(n0 + r) * DM + k0 + threadIdx.x] = t[threadIdx.x][r];
}

// -------------------- gating (+ fused x -> tf32 conversion) -----------------
__global__ void k_gate(const float* __restrict__ x,
                       const float* __restrict__ gw,
                       const float* __restrict__ gb) {
    int warp = (blockIdx.x * blockDim.x + threadIdx.x) >> 5;
    int lane = threadIdx.x & 31;
    if (warp >= NT) return;
    const float* xr = x + (size_t)warp * DM;
    uint32_t* xt = g_xt + (size_t)warp * DM;
    float acc[NE];
#pragma unroll
    for (int e = 0; e < NE; e++) acc[e] = 0.f;
    for (int k = lane; k < DM; k += 32) {
        float xv = xr[k];
        xt[k] = f2tf(xv);
#pragma unroll
        for (int e = 0; e < NE; e++) acc[e] += xv * gw[k * NE + e];
    }
#pragma unroll
    for (int e = 0; e < NE; e++)
#pragma unroll
        for (int off = 16; off; off >>= 1)
            acc[e] += __shfl_xor_sync(0xffffffffu, acc[e], off);
    if (lane == 0) {
#pragma unroll
        for (int e = 0; e < NE; e++) acc[e] += gb[e];
        int e0 = 0; float s0 = acc[0];
#pragma unroll
        for (int e = 1; e < NE; e++) if (acc[e] > s0) { s0 = acc[e]; e0 = e; }
        int e1 = -1; float s1 = -3.4e38f;
#pragma unroll
        for (int e = 0; e < NE; e++) if (e != e0 && acc[e] > s1) { s1 = acc[e]; e1 = e; }
        g_tokE[2*warp]   = e0;  g_tokS[2*warp]   = s0;
        g_tokE[2*warp+1] = e1;  g_tokS[2*warp+1] = s1;
        atomicAdd(&g_count[e0], 1);
        atomicAdd(&g_count[e1], 1);
    }
}

// -------------------- prefix (128-aligned) + tile->expert -------------------
__global__ void k_prefix() {
    if (threadIdx.x == 0) {
        int b = 0; g_base[0] = 0;
        for (int e = 0; e < NE; e++) {
            g_cursor[e] = b;
            b += ((g_count[e] + 127) >> 7) << 7;
            g_base[e+1] = b;
        }
    }
    __syncthreads();
    for (int t = threadIdx.x; t < MAX_TILES; t += blockDim.x) {
        int r = t << 7;
        int e = -1;
        for (int q = 0; q < NE; q++)
            if (r >= g_base[q] && r < g_base[q+1]) e = q;
        g_tileExpert[t] = e;
    }
}

__global__ void k_scatter() {
    int i = blockIdx.x * blockDim.x + threadIdx.x;
    if (i >= NT * 2) return;
    int e = g_tokE[i];
    int p = atomicAdd(&g_cursor[e], 1);
    g_rowToken[p]  = i >> 1;
    g_rowWeight[p] = g_tokS[i];
}

// -------------------- pipelined tf32 grouped GEMM ---------------------------
// CTA 128x128, 128 threads (4 warps 2x2, warp tile 64x64), BK=32, 3-stage
// cp.async, ldmatrix fragment loads, 2 CTAs/SM.
// Grid: (col, tile) -- col fastest so one row-tile's A is L2-resident across
// all 8 col-blocks (A DRAM traffic / phase: 2.1GB -> ~270MB).
template<int PHASE>
__global__ void __launch_bounds__(128, 2)
k_gemm(const float* __restrict__ Bias, float* __restrict__ Out) {
    extern __shared__ char smem[];
    int e = g_tileExpert[blockIdx.y];
    if (e < 0) return;
    const int rowBase = blockIdx.y * 128, colBase = blockIdx.x * 128;
    const int tid = threadIdx.x, lane = tid & 31, wid = tid >> 5;

    float* sBias = (float*)smem;
    sBias[tid] = Bias[e * DM + colBase + tid];

    const uint32_t sb = smem_u32(smem) + 1024;

    // ---- producer: 8 A-chunks + 8 B-chunks (16B) per thread per stage ----
    const int tr = tid >> 3, ch = tid & 7;                 // tr 0..15, ch 0..7
    // swizzle term depends only on (row&7) == (tr&7): invariant across i*16 rows
    const uint32_t dOff0 = tr * 128 + ((ch * 16) ^ ((tr & 7) << 4));
    const char* wT = (const char*)((PHASE == 1 ? g_w1t : g_w2t) + ((size_t)e << 20));
    const char* aBase = (PHASE == 1) ? (const char*)g_xt
                                     : (const char*)(g_hx + (size_t)rowBase * DM);
    uint32_t aOff[8], aSz[8], bOff[8];
#pragma unroll
    for (int i = 0; i < 8; i++) {
        int row = tr + 16 * i;
        if (PHASE == 1) {
            int tok = g_rowToken[rowBase + row];
            aOff[i] = (uint32_t)(tok < 0 ? 0 : tok) * 4096u + ch * 16;
            aSz[i]  = (tok < 0) ? 0u : 16u;
        } else {
            aOff[i] = (uint32_t)row * 4096u + ch * 16;
            aSz[i]  = 16u;
        }
        bOff[i] = (uint32_t)(colBase + row) * 4096u + ch * 16;
    }

#define PRODUCE(STAGE, KB)                                                      \
    {                                                                           \
        uint32_t base_ = sb + (STAGE) * STG;                                    \
        _Pragma("unroll")                                                       \
        for (int i_ = 0; i_ < 8; i_++) {                                        \
            cp16(base_ + dOff0 + i_ * 2048,         aBase + aOff[i_] + (KB), aSz[i_]); \
            cp16(base_ + 16384 + dOff0 + i_ * 2048, wT + bOff[i_] + (KB), 16); \
        }                                                                       \
    }

    PRODUCE(0, 0);    cp_commit();
    PRODUCE(1, 128);  cp_commit();

    // ---- consumer: ldmatrix addressing ----
    const int g = lane >> 2, tig = lane & 3;
    const int warpM = wid >> 1, warpN = wid & 1;
    const int lm = lane >> 3, lj = lane & 7;       // matrix idx, row within matrix
    const uint32_t swzMask = (uint32_t)lj << 4;
    const uint32_t aHalf = (uint32_t)(lm >> 1) << 4;   // A: m0,m1 half0; m2,m3 half1
    const uint32_t bHalf = (uint32_t)(lm & 1) << 4;    // B: m0,m2 half0; m1,m3 half1
    uint32_t aRow[4], bRow[4];
#pragma unroll
    for (int ma = 0; ma < 4; ma++)
        aRow[ma] = (uint32_t)(warpM * 64 + ma * 16 + (lm & 1) * 8 + lj) * 128;
#pragma unroll
    for (int p = 0; p < 4; p++)
        bRow[p] = 16384u + (uint32_t)(warpN * 64 + p * 16 + (lm >> 1) * 8 + lj) * 128;

    float c[4][8][4];
#pragma unroll
    for (int i = 0; i < 4; i++)
#pragma unroll
        for (int j = 0; j < 8; j++)
#pragma unroll
            for (int q = 0; q < 4; q++) c[i][j][q] = 0.f;

    for (int kk = 0; kk < 32; kk++) {
        cp_wait1();
        __syncthreads();
        if (kk + 2 < 32) {
            int s = (kk + 2) % NSTAGE;
            int kB = (kk + 2) * 128;
            PRODUCE(s, kB);
        }
        cp_commit();   // empty group in tail keeps wait_group<1> counting uniform

        const uint32_t stgA = sb + (kk % NSTAGE) * STG;
#pragma unroll
        for (int k8 = 0; k8 < 4; k8++) {
            const uint32_t kterm = (uint32_t)k8 * 32;
            uint32_t a[4][4], b[4][4];
#pragma unroll
            for (int ma = 0; ma < 4; ma++)
                ldsm4(a[ma], stgA + aRow[ma] + ((kterm + aHalf) ^ swzMask));
#pragma unroll
            for (int p = 0; p < 4; p++)
                ldsm4(b[p], stgA + bRow[p] + ((kterm + bHalf) ^ swzMask));
#pragma unroll
            for (int ma = 0; ma < 4; ma++)
#pragma unroll
                for (int nb = 0; nb < 8; nb++)
                    mma8(c[ma][nb], a[ma], &b[nb >> 1][(nb & 1) * 2]);
        }
    }
#undef PRODUCE

    // ---- epilogue ----
#pragma unroll
    for (int ma = 0; ma < 4; ma++) {
#pragma unroll
        for (int half = 0; half < 2; half++) {
            int grow = rowBase + warpM * 64 + ma * 16 + g + half * 8;
            if (PHASE == 1) {
                uint32_t* hrow = g_hx + (size_t)grow * DM + colBase;
#pragma unroll
                for (int nb = 0; nb < 8; nb++) {
                    int cn = warpN * 64 + nb * 8 + tig * 2;
                    float v0 = c[ma][nb][half*2+0] + sBias[cn];
                    float v1 = c[ma][nb][half*2+1] + sBias[cn+1];
                    v0 = fmaxf(v0, 0.f); v1 = fmaxf(v1, 0.f);
                    uint2 u; u.x = f2tf(v0); u.y = f2tf(v1);
                    *(uint2*)(hrow + cn) = u;
                }
            } else {
                int tok = g_rowToken[grow];
                if (tok >= 0) {
                    float w = g_rowWeight[grow];
                    float* orow = Out + (size_t)tok * DM + colBase;
#pragma unroll
                    for (int nb = 0; nb < 8; nb++) {
                        int cn = warpN * 64 + nb * 8 + tig * 2;
                        float v0 = (c[ma][nb][half*2+0] + sBias[cn])   * w;
                        float v1 = (c[ma][nb][half*2+1] + sBias[cn+1]) * w;
                        asm volatile("red.global.add.v2.f32 [%0], {%1,%2};"
                                     :: "l"(orow + cn), "f"(v0), "f"(v1) : "memory");
                    }
                }
            }
        }
    }
}

// -------------------- launch -----------------------------------------------
extern "C" void kernel_launch(void* const* d_in, const int* in_sizes, int n_in,
                              void* d_out, int out_size) {
    const float* x  = (const float*)d_in[0];
    const float* gw = (const float*)d_in[1];
    const float* gb = (const float*)d_in[2];
    const float* w1 = (const float*)d_in[3];
    const float* b1 = (const float*)d_in[4];
    const float* w2 = (const float*)d_in[5];
    const float* b2 = (const float*)d_in[6];
    float* out = (float*)d_out;

    static int smemSet = 0;
    if (!smemSet) {
        cudaFuncSetAttribute(k_gemm<1>, cudaFuncAttributeMaxDynamicSharedMemorySize, SMEM_TOTAL);
        cudaFuncSetAttribute(k_gemm<2>, cudaFuncAttributeMaxDynamicSharedMemorySize, SMEM_TOTAL);
        smemSet = 1;
    }

    k_init<<<512, 256>>>(out);
    k_transpose<<<dim3(32, 32, NE), dim3(32, 8)>>>(w1, 0);
    k_transpose<<<dim3(32, 32, NE), dim3(32, 8)>>>(w2, 1);
    k_gate<<<NT / 8, 256>>>(x, gw, gb);
    k_prefix<<<1, 128>>>();
    k_scatter<<<NT * 2 / 256, 256>>>();
    dim3 gg(DM / 128, MAX_TILES);
    k_gemm<1><<<gg, 128, SMEM_TOTAL>>>(b1, nullptr);
    k_gemm<2><<<gg, 128, SMEM_TOTAL>>>(b2, out);
}